// round 2
// baseline (speedup 1.0000x reference)
#include <cuda_runtime.h>
#include <cuda_bf16.h>

#define NPTS 8192
#define CH   32
#define TILE 128
#define MT   (NPTS / TILE)            // 64 tiles per dim
#define NTILES (MT * (MT + 1) / 2)    // 2080 upper-triangle tile pairs

// Scratch (no allocations allowed in kernel_launch)
__device__ float g_sq[NPTS];
__device__ float g_partial[NTILES];

// ---------------------------------------------------------------------------
// Kernel A: per-point squared norms. x layout is [C][N] (channel-major).
// IMPORTANT: uses non-FMA rounded products with a 4-accumulator tree reduction
// so that sq_i and the tile kernel's sequential-FMA dot_ii differ by generic
// fp32 rounding noise, replicating the reference's (XLA reduce vs einsum)
// diagonal behavior: d2_ii = 2*(sq_i - dot_ii) ~ +-5e-6 instead of exactly 0.
// ---------------------------------------------------------------------------
__global__ void norms_kernel(const float* __restrict__ x) {
    int n = blockIdx.x * blockDim.x + threadIdx.x;
    if (n < NPTS) {
        float a0 = 0.f, a1 = 0.f, a2 = 0.f, a3 = 0.f;
#pragma unroll
        for (int c = 0; c < CH; c += 4) {
            float v0 = x[(c + 0) * NPTS + n];
            float v1 = x[(c + 1) * NPTS + n];
            float v2 = x[(c + 2) * NPTS + n];
            float v3 = x[(c + 3) * NPTS + n];
            a0 = __fadd_rn(a0, __fmul_rn(v0, v0));
            a1 = __fadd_rn(a1, __fmul_rn(v1, v1));
            a2 = __fadd_rn(a2, __fmul_rn(v2, v2));
            a3 = __fadd_rn(a3, __fmul_rn(v3, v3));
        }
        g_sq[n] = __fadd_rn(__fadd_rn(a0, a1), __fadd_rn(a2, a3));
    }
}

// ---------------------------------------------------------------------------
// Kernel B: one block per (I,J) tile pair with J >= I.
// 128x128 dot products (K=32) with 8x8 register micro-tiles (sequential FMA
// over c), clipped-linear loss epilogue, deterministic block reduction.
// Off-diagonal tiles weighted x2 (symmetry). Diagonal entries go through the
// SAME epilogue (no special case) so they pick up the sq-vs-dot rounding
// noise, matching the reference.
// ---------------------------------------------------------------------------
__global__ __launch_bounds__(256, 2) void tile_kernel(const float* __restrict__ x) {
    __shared__ float4 As[CH][TILE / 4];   // 16 KB
    __shared__ float4 Bs[CH][TILE / 4];   // 16 KB
    __shared__ float  sqA[TILE];
    __shared__ float  sqB[TILE];
    __shared__ float  red[256];

    // Decode blockIdx.x -> (I, J), row-major over the upper triangle.
    int bid = blockIdx.x;
    int I = 0, rem = bid;
    while (rem >= MT - I) { rem -= MT - I; ++I; }
    int J = I + rem;

    int tid = threadIdx.x;

    // Load A and B tiles: [CH][128] floats each, coalesced float4 loads.
    const float4* x4 = reinterpret_cast<const float4*>(x);
#pragma unroll
    for (int k = tid; k < CH * (TILE / 4); k += 256) {
        int c = k >> 5;        // TILE/4 == 32
        int q = k & 31;
        As[c][q] = x4[(c * NPTS + I * TILE) / 4 + q];
        Bs[c][q] = x4[(c * NPTS + J * TILE) / 4 + q];
    }
    if (tid < TILE) {
        sqA[tid] = g_sq[I * TILE + tid];
        sqB[tid] = g_sq[J * TILE + tid];
    }
    __syncthreads();

    int tx = tid & 15;   // i-dim micro-tile index (16)
    int ty = tid >> 4;   // j-dim micro-tile index (16)

    float acc[8][8];
#pragma unroll
    for (int a = 0; a < 8; ++a)
#pragma unroll
        for (int b = 0; b < 8; ++b) acc[a][b] = 0.f;

#pragma unroll 4
    for (int c = 0; c < CH; ++c) {
        float4 a0 = As[c][tx * 2 + 0];
        float4 a1 = As[c][tx * 2 + 1];
        float4 b0 = Bs[c][ty * 2 + 0];
        float4 b1 = Bs[c][ty * 2 + 1];
        float av[8] = {a0.x, a0.y, a0.z, a0.w, a1.x, a1.y, a1.z, a1.w};
        float bv[8] = {b0.x, b0.y, b0.z, b0.w, b1.x, b1.y, b1.z, b1.w};
#pragma unroll
        for (int ii = 0; ii < 8; ++ii)
#pragma unroll
            for (int jj = 0; jj < 8; ++jj)
                acc[ii][jj] = fmaf(av[ii], bv[jj], acc[ii][jj]);
    }

    // Epilogue: d2 = sq_i + sq_j - 2*dot ; f(d) = 1.5 d - 0.5 d^2 - 1 on [0,2], else 0.
    // Diagonal entries flow through the same path: d2 = 2*(sq_i - dot_ii) is
    // small rounding noise; max(0) + sqrt reproduces the reference's bias.
    float local = 0.f;
    bool diag = (I == J);
    int li0 = tx * 8;
    int lj0 = ty * 8;
#pragma unroll
    for (int ii = 0; ii < 8; ++ii) {
        float si = sqA[li0 + ii];
#pragma unroll
        for (int jj = 0; jj < 8; ++jj) {
            float d2 = fmaf(-2.f, acc[ii][jj], si + sqB[lj0 + jj]);
            if (d2 < 4.f) {
                d2 = fmaxf(d2, 0.f);
                float d = sqrtf(d2);
                local += fmaf(1.5f, d, fmaf(-0.5f, d2, -1.f));
            }
        }
    }
    if (!diag) local *= 2.f;   // symmetry: (I,J) and (J,I) identical

    // Deterministic block reduction.
    red[tid] = local;
    __syncthreads();
#pragma unroll
    for (int s = 128; s > 0; s >>= 1) {
        if (tid < s) red[tid] += red[tid + s];
        __syncthreads();
    }
    if (tid == 0) g_partial[bid] = red[0];
}

// ---------------------------------------------------------------------------
// Kernel C: deterministic final reduction of per-tile partials; scale by 0.25.
// ---------------------------------------------------------------------------
__global__ void reduce_kernel(float* __restrict__ out) {
    __shared__ float red[256];
    int tid = threadIdx.x;
    float s = 0.f;
    for (int i = tid; i < NTILES; i += 256) s += g_partial[i];
    red[tid] = s;
    __syncthreads();
#pragma unroll
    for (int k = 128; k > 0; k >>= 1) {
        if (tid < k) red[tid] += red[tid + k];
        __syncthreads();
    }
    if (tid == 0) out[0] = 0.25f * red[0];
}

// ---------------------------------------------------------------------------
extern "C" void kernel_launch(void* const* d_in, const int* in_sizes, int n_in,
                              void* d_out, int out_size) {
    const float* x = (const float*)d_in[0];   // [1, 32, 8192] fp32, channel-major
    float* out = (float*)d_out;

    norms_kernel<<<(NPTS + 255) / 256, 256>>>(x);
    tile_kernel<<<NTILES, 256>>>(x);
    reduce_kernel<<<1, 256>>>(out);
}

// round 4
// speedup vs baseline: 1.7971x; 1.7971x over previous
#include <cuda_runtime.h>
#include <cuda_bf16.h>
#include <cstdint>

#define NPTS   8192
#define CH     32
#define TILE   128
#define MT     64                      // NPTS / TILE
#define NTILES 2080                    // MT*(MT+1)/2 upper-triangle tile pairs
#define NPREP  32                      // prep blocks (8192 / 256)
#define LDPW   20                      // padded row stride in b32 words (80 bytes)

// ---------------- device scratch (no allocations allowed) -------------------
__device__ float    g_sq[NPTS];
__device__ uint32_t g_xbf[NPTS * 16];     // [n][16] bf16x2: point-major rows, 32 channels
__device__ float    g_partial[NTILES];
__device__ float    g_diagpart[NPREP];

// ---------------------------------------------------------------------------
// Kernel A (prep): per-point sq (non-FMA tree) + sequential-FMA self-dot ->
// diagonal loss with the reference's rounding-noise structure (identical to
// the R2 passing pipeline), plus fp32 -> bf16 pack into point-major rows.
// ---------------------------------------------------------------------------
__global__ void prep_kernel(const float* __restrict__ x) {
    int n = blockIdx.x * 256 + threadIdx.x;

    float v[CH];
#pragma unroll
    for (int c = 0; c < CH; ++c) v[c] = x[c * NPTS + n];

    // sq: non-FMA rounded products, 4-accumulator tree (XLA-reduce flavor)
    float a0 = 0.f, a1 = 0.f, a2 = 0.f, a3 = 0.f;
#pragma unroll
    for (int c = 0; c < CH; c += 4) {
        a0 = __fadd_rn(a0, __fmul_rn(v[c + 0], v[c + 0]));
        a1 = __fadd_rn(a1, __fmul_rn(v[c + 1], v[c + 1]));
        a2 = __fadd_rn(a2, __fmul_rn(v[c + 2], v[c + 2]));
        a3 = __fadd_rn(a3, __fmul_rn(v[c + 3], v[c + 3]));
    }
    float sq = __fadd_rn(__fadd_rn(a0, a1), __fadd_rn(a2, a3));
    g_sq[n] = sq;

    // self-dot: sequential FMA chain (GEMM flavor) -> diagonal noise d2 ~ +-eps
    float dot = 0.f;
#pragma unroll
    for (int c = 0; c < CH; ++c) dot = fmaf(v[c], v[c], dot);

    float d2 = fmaf(-2.f, dot, __fadd_rn(sq, sq));
    float f = 0.f;
    if (d2 < 4.f) {
        d2 = fmaxf(d2, 0.f);
        float d = sqrtf(d2);
        f = fmaf(1.5f, d, fmaf(-0.5f, d2, -1.f));
    }

    // bf16 pack: row n = 32 channels contiguous (16 bf16x2 words)
    uint32_t* dst = &g_xbf[n * 16];
#pragma unroll
    for (int c2 = 0; c2 < 16; ++c2) {
        __nv_bfloat162 p = __floats2bfloat162_rn(v[2 * c2], v[2 * c2 + 1]);
        dst[c2] = *reinterpret_cast<uint32_t*>(&p);
    }

    __shared__ float red[256];
    int t = threadIdx.x;
    red[t] = f;
    __syncthreads();
#pragma unroll
    for (int s = 128; s > 0; s >>= 1) {
        if (t < s) red[t] += red[t + s];
        __syncthreads();
    }
    if (t == 0) g_diagpart[blockIdx.x] = red[0];
}

// ---------------------------------------------------------------------------
// mma.sync m16n8k16 bf16 (sm_80+ baseline PTX; portable to plain sm_103).
// A row-major (m16 x k16), B col-major (k16 x n8) == Bt row-major (n8 x k16).
// ---------------------------------------------------------------------------
__device__ __forceinline__ void hmma16816(float* c, const uint32_t* a, const uint32_t* b) {
    asm volatile(
        "mma.sync.aligned.m16n8k16.row.col.f32.bf16.bf16.f32 "
        "{%0,%1,%2,%3}, {%4,%5,%6,%7}, {%8,%9}, {%0,%1,%2,%3};"
        : "+f"(c[0]), "+f"(c[1]), "+f"(c[2]), "+f"(c[3])
        : "r"(a[0]), "r"(a[1]), "r"(a[2]), "r"(a[3]), "r"(b[0]), "r"(b[1]));
}

// ---------------------------------------------------------------------------
// Kernel B (tile): one CTA per (I,J) tile pair, J >= I. bf16 HMMA Gram as a
// SCREEN: elements with d2_bf16 < 8 (true cut 4, bf16 error << 4) get an
// exact fp32 recompute. Diagonal entries (gi==gj) excluded (done in prep).
// 8 warps; warp w owns rows (w%4)*32..+31 and cols (w/4)*64..+63.
// ---------------------------------------------------------------------------
__global__ __launch_bounds__(256) void tile_kernel(const float* __restrict__ x) {
    __shared__ __align__(16) uint32_t As[TILE * LDPW];   // 10 KB, padded 80B rows
    __shared__ __align__(16) uint32_t Bs[TILE * LDPW];   // 10 KB
    __shared__ float sqA[TILE];
    __shared__ float sqB[TILE];
    __shared__ float red[256];

    int tid = threadIdx.x;
    int wid = tid >> 5;
    int lane = tid & 31;

    // decode blockIdx -> (I, J) over upper triangle
    int bid = blockIdx.x;
    int I = 0, rem = bid;
    while (rem >= MT - I) { rem -= MT - I; ++I; }
    int J = I + rem;

    // fill A/B tiles: 256 threads = 2 tiles x 128 rows; 4x uint4 per row
    {
        int row   = tid & 127;
        int which = tid >> 7;                  // 0 -> A, 1 -> B
        int base  = (which ? J : I) * TILE + row;
        const uint4* src = reinterpret_cast<const uint4*>(&g_xbf[base * 16]);
        uint4* dst = reinterpret_cast<uint4*>((which ? Bs : As) + row * LDPW);
#pragma unroll
        for (int q = 0; q < 4; ++q) dst[q] = src[q];
        if (which) sqB[row] = g_sq[base];
        else       sqA[row] = g_sq[base];
    }
    __syncthreads();

    int m0 = (wid & 3) * 32;     // row block of this warp
    int n0 = (wid >> 2) * 64;    // col block of this warp
    int qr = lane >> 2;          // 0..7
    int qc = lane & 3;           // 0..3

    // A fragments: a[mi][kf][4]
    uint32_t afr[2][2][4];
#pragma unroll
    for (int mi = 0; mi < 2; ++mi) {
        int r0 = m0 + mi * 16 + qr;
        int r1 = r0 + 8;
#pragma unroll
        for (int kf = 0; kf < 2; ++kf) {
            int kw = kf * 8 + qc;
            afr[mi][kf][0] = As[r0 * LDPW + kw];
            afr[mi][kf][1] = As[r1 * LDPW + kw];
            afr[mi][kf][2] = As[r0 * LDPW + kw + 4];
            afr[mi][kf][3] = As[r1 * LDPW + kw + 4];
        }
    }

    // per-lane row norms (4 distinct rows) and global row ids
    float siv[2][2];
    int   giv[2][2];
#pragma unroll
    for (int mi = 0; mi < 2; ++mi) {
        siv[mi][0] = sqA[m0 + mi * 16 + qr];
        siv[mi][1] = sqA[m0 + mi * 16 + qr + 8];
        giv[mi][0] = I * TILE + m0 + mi * 16 + qr;
        giv[mi][1] = giv[mi][0] + 8;
    }

    float local = 0.f;

#pragma unroll
    for (int nj = 0; nj < 8; ++nj) {
        int jrow = n0 + nj * 8 + qr;           // Bt row (point index within tile)
        uint32_t bfr[2][2];
#pragma unroll
        for (int kf = 0; kf < 2; ++kf) {
            int kw = kf * 8 + qc;
            bfr[kf][0] = Bs[jrow * LDPW + kw];
            bfr[kf][1] = Bs[jrow * LDPW + kw + 4];
        }

        float acc[2][4];
#pragma unroll
        for (int mi = 0; mi < 2; ++mi) {
            acc[mi][0] = acc[mi][1] = acc[mi][2] = acc[mi][3] = 0.f;
            hmma16816(acc[mi], afr[mi][0], bfr[0]);
            hmma16816(acc[mi], afr[mi][1], bfr[1]);
        }

        // epilogue for this n-fragment: cols n0+nj*8 + 2*qc, +1
        int colb = n0 + nj * 8 + 2 * qc;
        float sj0 = sqB[colb];
        float sj1 = sqB[colb + 1];
        int   gj0 = J * TILE + colb;
        int   gj1 = gj0 + 1;

#pragma unroll
        for (int mi = 0; mi < 2; ++mi) {
#pragma unroll
            for (int e = 0; e < 4; ++e) {
                int   rh = e >> 1;                       // row half (groupID / +8)
                float sj = (e & 1) ? sj1 : sj0;
                int   gj = (e & 1) ? gj1 : gj0;
                float d2s = fmaf(-2.f, acc[mi][e], siv[mi][rh] + sj);
                if (d2s < 8.f) {                         // screen (rare)
                    int gi = giv[mi][rh];
                    if (gi != gj) {
                        float dt = 0.f;
#pragma unroll
                        for (int c = 0; c < CH; ++c)
                            dt = fmaf(x[c * NPTS + gi], x[c * NPTS + gj], dt);
                        float e2 = fmaf(-2.f, dt, siv[mi][rh] + sj);
                        if (e2 < 4.f) {
                            e2 = fmaxf(e2, 0.f);
                            float d = sqrtf(e2);
                            local += fmaf(1.5f, d, fmaf(-0.5f, e2, -1.f));
                        }
                    }
                }
            }
        }
    }

    if (I != J) local *= 2.f;   // symmetry: (I,J) and (J,I) identical

    // deterministic block reduction
    red[tid] = local;
    __syncthreads();
#pragma unroll
    for (int s = 128; s > 0; s >>= 1) {
        if (tid < s) red[tid] += red[tid + s];
        __syncthreads();
    }
    if (tid == 0) g_partial[bid] = red[0];
}

// ---------------------------------------------------------------------------
// Kernel C: deterministic final reduction; scale by 0.25.
// ---------------------------------------------------------------------------
__global__ void reduce_kernel(float* __restrict__ out) {
    __shared__ float red[256];
    int t = threadIdx.x;
    float s = 0.f;
    for (int i = t; i < NTILES; i += 256) s += g_partial[i];
    if (t < NPREP) s += g_diagpart[t];
    red[t] = s;
    __syncthreads();
#pragma unroll
    for (int k = 128; k > 0; k >>= 1) {
        if (t < k) red[t] += red[t + k];
        __syncthreads();
    }
    if (t == 0) out[0] = 0.25f * red[0];
}

// ---------------------------------------------------------------------------
extern "C" void kernel_launch(void* const* d_in, const int* in_sizes, int n_in,
                              void* d_out, int out_size) {
    const float* x = (const float*)d_in[0];   // [1, 32, 8192] fp32, channel-major
    float* out = (float*)d_out;

    prep_kernel<<<NPREP, 256>>>(x);
    tile_kernel<<<NTILES, 256>>>(x);
    reduce_kernel<<<1, 256>>>(out);
}

// round 5
// speedup vs baseline: 1.9880x; 1.1063x over previous
#include <cuda_runtime.h>
#include <cuda_bf16.h>
#include <cstdint>

#define NPTS   8192
#define CH     32
#define TILE   256
#define MT     32                      // NPTS / TILE
#define NTILES 528                     // MT*(MT+1)/2 upper-triangle tile pairs
#define NPREP  64                      // prep blocks (8192 / 128)
#define LDPW   20                      // padded row stride in b32 words (80 bytes)

// ---------------- device scratch (no allocations allowed) -------------------
__device__ float    g_sq[NPTS];
__device__ uint32_t g_xbf[NPTS * 16];     // [n][16] bf16x2: point-major rows, 32 channels
__device__ float    g_partial[NTILES];
__device__ float    g_diagpart[NPREP];

// ---------------------------------------------------------------------------
// Kernel A (prep): per-point sq (non-FMA tree) + sequential-FMA self-dot ->
// diagonal loss with the reference's rounding-noise structure (bit-identical
// per-point arithmetic to the passing R2/R4 pipeline), plus fp32 -> bf16 pack.
// Grid widened to 64 CTAs of 128 for latency hiding.
// ---------------------------------------------------------------------------
__global__ void prep_kernel(const float* __restrict__ x) {
    int n = blockIdx.x * 128 + threadIdx.x;

    float v[CH];
#pragma unroll
    for (int c = 0; c < CH; ++c) v[c] = x[c * NPTS + n];

    // sq: non-FMA rounded products, 4-accumulator tree (XLA-reduce flavor)
    float a0 = 0.f, a1 = 0.f, a2 = 0.f, a3 = 0.f;
#pragma unroll
    for (int c = 0; c < CH; c += 4) {
        a0 = __fadd_rn(a0, __fmul_rn(v[c + 0], v[c + 0]));
        a1 = __fadd_rn(a1, __fmul_rn(v[c + 1], v[c + 1]));
        a2 = __fadd_rn(a2, __fmul_rn(v[c + 2], v[c + 2]));
        a3 = __fadd_rn(a3, __fmul_rn(v[c + 3], v[c + 3]));
    }
    float sq = __fadd_rn(__fadd_rn(a0, a1), __fadd_rn(a2, a3));
    g_sq[n] = sq;

    // self-dot: sequential FMA chain (GEMM flavor) -> diagonal noise d2 ~ +-eps
    float dot = 0.f;
#pragma unroll
    for (int c = 0; c < CH; ++c) dot = fmaf(v[c], v[c], dot);

    float d2 = fmaf(-2.f, dot, __fadd_rn(sq, sq));
    float f = 0.f;
    if (d2 < 4.f) {
        d2 = fmaxf(d2, 0.f);
        float d = sqrtf(d2);
        f = fmaf(1.5f, d, fmaf(-0.5f, d2, -1.f));
    }

    // bf16 pack: row n = 32 channels contiguous (16 bf16x2 words)
    uint32_t* dst = &g_xbf[n * 16];
#pragma unroll
    for (int c2 = 0; c2 < 16; ++c2) {
        __nv_bfloat162 p = __floats2bfloat162_rn(v[2 * c2], v[2 * c2 + 1]);
        dst[c2] = *reinterpret_cast<uint32_t*>(&p);
    }

    __shared__ float red[128];
    int t = threadIdx.x;
    red[t] = f;
    __syncthreads();
#pragma unroll
    for (int s = 64; s > 0; s >>= 1) {
        if (t < s) red[t] += red[t + s];
        __syncthreads();
    }
    if (t == 0) g_diagpart[blockIdx.x] = red[0];
}

// ---------------------------------------------------------------------------
// mma.sync m16n8k16 bf16 (sm_80+ baseline PTX; portable to plain sm_103).
// ---------------------------------------------------------------------------
__device__ __forceinline__ void hmma16816(float* c, const uint32_t* a, const uint32_t* b) {
    asm volatile(
        "mma.sync.aligned.m16n8k16.row.col.f32.bf16.bf16.f32 "
        "{%0,%1,%2,%3}, {%4,%5,%6,%7}, {%8,%9}, {%0,%1,%2,%3};"
        : "+f"(c[0]), "+f"(c[1]), "+f"(c[2]), "+f"(c[3])
        : "r"(a[0]), "r"(a[1]), "r"(a[2]), "r"(a[3]), "r"(b[0]), "r"(b[1]));
}

// ---------------------------------------------------------------------------
// Cold path: lane-exact fp32 recompute of this lane's 8 rows x 32 cols.
// Runs only when the bf16 screen flags (probability ~1e-9 per lane) and is
// exact, so correctness never depends on it being rare.
// ---------------------------------------------------------------------------
__device__ __noinline__ float slow_lane(const float* __restrict__ x,
                                        int I, int J, int m0, int n0,
                                        int qr, int qc) {
    float acc = 0.f;
#pragma unroll 1
    for (int r = 0; r < 8; ++r) {                 // mi = r>>1, rh = r&1
        int gi = I * TILE + m0 + (r >> 1) * 16 + qr + (r & 1) * 8;
        float si = g_sq[gi];
#pragma unroll 1
        for (int cidx = 0; cidx < 32; ++cidx) {   // nj = cidx>>1, cb = cidx&1
            int gj = J * TILE + n0 + (cidx >> 1) * 8 + 2 * qc + (cidx & 1);
            if (gi == gj) continue;
            float dt = 0.f;
#pragma unroll
            for (int c = 0; c < CH; ++c)
                dt = fmaf(x[c * NPTS + gi], x[c * NPTS + gj], dt);
            float e2 = fmaf(-2.f, dt, si + g_sq[gj]);
            if (e2 < 4.f) {
                e2 = fmaxf(e2, 0.f);
                float d = sqrtf(e2);
                acc += fmaf(1.5f, d, fmaf(-0.5f, e2, -1.f));
            }
        }
    }
    return acc;
}

// ---------------------------------------------------------------------------
// Kernel B (tile): one CTA per (I,J) 256x256 tile pair, J >= I, 8 warps.
// Warp w owns rows (w&3)*64 .. +63 and cols (w>>2)*128 .. +127.
// Off-diagonal tiles: branch-free min-screen epilogue + deferred exact path.
// Diagonal tiles: per-element branchy exact path (diagonal always flags).
// ---------------------------------------------------------------------------
__global__ __launch_bounds__(256) void tile_kernel(const float* __restrict__ x) {
    __shared__ __align__(16) uint32_t As[TILE * LDPW];   // 20 KB
    __shared__ __align__(16) uint32_t Bs[TILE * LDPW];   // 20 KB
    __shared__ float sqA[TILE];
    __shared__ float sqB[TILE];
    __shared__ float red[256];

    int tid = threadIdx.x;
    int wid = tid >> 5;
    int lane = tid & 31;

    // decode blockIdx -> (I, J) over upper triangle
    int bid = blockIdx.x;
    int I = 0, rem = bid;
    while (rem >= MT - I) { rem -= MT - I; ++I; }
    int J = I + rem;

    // fill A/B tiles: 256 threads, 2 tiles x 256 rows -> 2 rows per thread
    {
        int which = tid >> 7;                  // 0 -> A, 1 -> B
        int r0 = tid & 127;
#pragma unroll
        for (int rr = 0; rr < 2; ++rr) {
            int row  = r0 + rr * 128;
            int base = (which ? J : I) * TILE + row;
            const uint4* src = reinterpret_cast<const uint4*>(&g_xbf[base * 16]);
            uint4* dst = reinterpret_cast<uint4*>((which ? Bs : As) + row * LDPW);
#pragma unroll
            for (int q = 0; q < 4; ++q) dst[q] = src[q];
            if (which) sqB[row] = g_sq[base];
            else       sqA[row] = g_sq[base];
        }
    }
    __syncthreads();

    int m0 = (wid & 3) * 64;     // row block of this warp (64 rows)
    int n0 = (wid >> 2) * 128;   // col block of this warp (128 cols)
    int qr = lane >> 2;          // 0..7
    int qc = lane & 3;           // 0..3

    // A fragments: afr[mi][kf][4], mi = 0..3 (16-row slabs)
    uint32_t afr[4][2][4];
#pragma unroll
    for (int mi = 0; mi < 4; ++mi) {
        int r0 = m0 + mi * 16 + qr;
        int r1 = r0 + 8;
#pragma unroll
        for (int kf = 0; kf < 2; ++kf) {
            int kw = kf * 8 + qc;
            afr[mi][kf][0] = As[r0 * LDPW + kw];
            afr[mi][kf][1] = As[r1 * LDPW + kw];
            afr[mi][kf][2] = As[r0 * LDPW + kw + 4];
            afr[mi][kf][3] = As[r1 * LDPW + kw + 4];
        }
    }

    // per-lane row norms (8 distinct rows)
    float siv[4][2];
#pragma unroll
    for (int mi = 0; mi < 4; ++mi) {
        siv[mi][0] = sqA[m0 + mi * 16 + qr];
        siv[mi][1] = sqA[m0 + mi * 16 + qr + 8];
    }

    float local = 0.f;

    if (I != J) {
        // ---- hot path: branch-free screen over 16 n-fragments ----
        float dmin = 1e30f;
#pragma unroll
        for (int nj = 0; nj < 16; ++nj) {
            int jrow = n0 + nj * 8 + qr;
            uint32_t bfr[2][2];
#pragma unroll
            for (int kf = 0; kf < 2; ++kf) {
                int kw = kf * 8 + qc;
                bfr[kf][0] = Bs[jrow * LDPW + kw];
                bfr[kf][1] = Bs[jrow * LDPW + kw + 4];
            }
            float acc[4][4];
#pragma unroll
            for (int mi = 0; mi < 4; ++mi) {
                acc[mi][0] = acc[mi][1] = acc[mi][2] = acc[mi][3] = 0.f;
                hmma16816(acc[mi], afr[mi][0], bfr[0]);
                hmma16816(acc[mi], afr[mi][1], bfr[1]);
            }
            int colb = n0 + nj * 8 + 2 * qc;
            float sj0 = sqB[colb];
            float sj1 = sqB[colb + 1];
#pragma unroll
            for (int mi = 0; mi < 4; ++mi) {
#pragma unroll
                for (int e = 0; e < 4; ++e) {
                    float s = siv[mi][e >> 1] + ((e & 1) ? sj1 : sj0);
                    dmin = fminf(dmin, fmaf(-2.f, acc[mi][e], s));
                }
            }
        }
        if (dmin < 8.f)   // conservative screen (true cut 4, bf16 error << 4)
            local = slow_lane(x, I, J, m0, n0, qr, qc);
        local *= 2.f;     // symmetry: (I,J) and (J,I) identical
    } else {
        // ---- diagonal tile: exact per-element path (diagonal always flags) ----
#pragma unroll
        for (int nj = 0; nj < 16; ++nj) {
            int jrow = n0 + nj * 8 + qr;
            uint32_t bfr[2][2];
#pragma unroll
            for (int kf = 0; kf < 2; ++kf) {
                int kw = kf * 8 + qc;
                bfr[kf][0] = Bs[jrow * LDPW + kw];
                bfr[kf][1] = Bs[jrow * LDPW + kw + 4];
            }
            float acc[4][4];
#pragma unroll
            for (int mi = 0; mi < 4; ++mi) {
                acc[mi][0] = acc[mi][1] = acc[mi][2] = acc[mi][3] = 0.f;
                hmma16816(acc[mi], afr[mi][0], bfr[0]);
                hmma16816(acc[mi], afr[mi][1], bfr[1]);
            }
            int colb = n0 + nj * 8 + 2 * qc;
            float sj0 = sqB[colb];
            float sj1 = sqB[colb + 1];
            int   gj0 = J * TILE + colb;
#pragma unroll
            for (int mi = 0; mi < 4; ++mi) {
#pragma unroll
                for (int e = 0; e < 4; ++e) {
                    int   rh = e >> 1;
                    float sj = (e & 1) ? sj1 : sj0;
                    int   gj = gj0 + (e & 1);
                    float si = siv[mi][rh];
                    float d2s = fmaf(-2.f, acc[mi][e], si + sj);
                    if (d2s < 8.f) {
                        int gi = I * TILE + m0 + mi * 16 + qr + rh * 8;
                        if (gi != gj) {
                            float dt = 0.f;
#pragma unroll
                            for (int c = 0; c < CH; ++c)
                                dt = fmaf(x[c * NPTS + gi], x[c * NPTS + gj], dt);
                            float e2 = fmaf(-2.f, dt, si + sj);
                            if (e2 < 4.f) {
                                e2 = fmaxf(e2, 0.f);
                                float d = sqrtf(e2);
                                local += fmaf(1.5f, d, fmaf(-0.5f, e2, -1.f));
                            }
                        }
                    }
                }
            }
        }
    }

    // deterministic block reduction
    red[tid] = local;
    __syncthreads();
#pragma unroll
    for (int s = 128; s > 0; s >>= 1) {
        if (tid < s) red[tid] += red[tid + s];
        __syncthreads();
    }
    if (tid == 0) g_partial[bid] = red[0];
}

// ---------------------------------------------------------------------------
// Kernel C: deterministic final reduction; scale by 0.25.
// ---------------------------------------------------------------------------
__global__ void reduce_kernel(float* __restrict__ out) {
    __shared__ float red[256];
    int t = threadIdx.x;
    float s = 0.f;
    for (int i = t; i < NTILES; i += 256) s += g_partial[i];
    if (t < NPREP) s += g_diagpart[t];
    red[t] = s;
    __syncthreads();
#pragma unroll
    for (int k = 128; k > 0; k >>= 1) {
        if (t < k) red[t] += red[t + k];
        __syncthreads();
    }
    if (t == 0) out[0] = 0.25f * red[0];
}

// ---------------------------------------------------------------------------
extern "C" void kernel_launch(void* const* d_in, const int* in_sizes, int n_in,
                              void* d_out, int out_size) {
    const float* x = (const float*)d_in[0];   // [1, 32, 8192] fp32, channel-major
    float* out = (float*)d_out;

    prep_kernel<<<NPREP, 128>>>(x);
    tile_kernel<<<NTILES, 256>>>(x);
    reduce_kernel<<<1, 256>>>(out);
}